// round 11
// baseline (speedup 1.0000x reference)
#include <cuda_runtime.h>
#include <cuda_fp16.h>
#include <cstdint>

// fullConv4d via fp16 mma.sync m16n8k16 (fp32 accum). M=spatial, N=co, K=ci16.
// R11: 3-kt-copy ALIGNED slab (every ldmatrix matrix = 128B-aligned contiguous ->
// 4 wf/LDSM.x4) + single-buffered staging + per-kh weights => 106KB smem = 2 CTA/SM.
// Inter-CTA overlap hides the per-plane cp.async latency.
// Prep kernels: x -> fp16 point-major [pt][ci16]; weights -> B-fragment order.

#define ST_T 1
#define ST_D 24
#define ST_W 576
#define ST_H 13824
#define ST_C 331776

#define HALFB   15360                       // 960 rows * 16B
#define COPYB   30720                       // 2 halves
#define SLABB   92160                       // 3 kt copies
#define WSB     13824                       // 27 taps * 512B (per-kh)
#define SMEM_BYTES (SLABB + WSB)            // 105984

__device__ uint4 g_xh[1327104];             // 663552 points * 32B (fp16, ci16)
__device__ uint4 g_wf[2592];                // 81 taps * 32 lanes * 16B

static __device__ __forceinline__ uint32_t smem_u32(const void* p) {
    uint32_t a;
    asm("{ .reg .u64 t; cvta.to.shared.u64 t, %1; cvt.u32.u64 %0, t; }" : "=r"(a) : "l"(p));
    return a;
}

static __device__ __forceinline__ uint32_t pack2(float a, float b) {
    __half2 h = __floats2half2_rn(a, b);
    return *reinterpret_cast<uint32_t*>(&h);
}

static __device__ __forceinline__ void cpa16(uint32_t dst, const void* src, uint32_t srcsz) {
    asm volatile("cp.async.cg.shared.global [%0], [%1], 16, %2;"
                 :: "r"(dst), "l"(src), "r"(srcsz));
}

static __device__ __forceinline__ void mma16816(float* d, uint32_t a0, uint32_t a1,
                                                uint32_t a2, uint32_t a3,
                                                uint32_t b0, uint32_t b1) {
    asm volatile(
        "mma.sync.aligned.m16n8k16.row.col.f32.f16.f16.f32 "
        "{%0,%1,%2,%3}, {%4,%5,%6,%7}, {%8,%9}, {%0,%1,%2,%3};"
        : "+f"(d[0]), "+f"(d[1]), "+f"(d[2]), "+f"(d[3])
        : "r"(a0), "r"(a1), "r"(a2), "r"(a3), "r"(b0), "r"(b1));
}

// ---- prep 1: x[b][ci][h][w][d][t] fp32 -> g_xh[(b,h,w,d,t)][ci16] fp16 ----
__global__ __launch_bounds__(256)
void prep_x_kernel(const float* __restrict__ x) {
    const int idx = blockIdx.x * 256 + threadIdx.x;          // 663552 points
    int r = idx;
    const int t = r % 24; r /= 24;
    const int d = r % 24; r /= 24;
    const int w = r % 24; r /= 24;
    const int h = r % 24;
    const int b = r / 24;
    const float* p = x + (size_t)b * 16 * ST_C + h * ST_H + w * ST_W + d * ST_D + t;
    uint32_t v[8];
    #pragma unroll
    for (int j = 0; j < 8; ++j)
        v[j] = pack2(p[(2 * j) * ST_C], p[(2 * j + 1) * ST_C]);
    g_xh[idx * 2]     = make_uint4(v[0], v[1], v[2], v[3]);
    g_xh[idx * 2 + 1] = make_uint4(v[4], v[5], v[6], v[7]);
}

// ---- prep 2: weights -> B-fragment order g_wf[tap][lane] ----
__global__ __launch_bounds__(256)
void prep_w_kernel(const float* __restrict__ wgt) {
    for (int i = threadIdx.x; i < 2592; i += 256) {
        const int tl = i >> 5, l5 = i & 31;
        const int gg = l5 >> 2, cc = (l5 & 3) << 1;
        const float* wp = wgt + tl;
        #define WG(co, ci) wp[((co) * 16 + (ci)) * 81]
        const uint32_t r0 = pack2(WG(gg, cc),         WG(gg, cc + 1));
        const uint32_t r1 = pack2(WG(gg, cc + 8),     WG(gg, cc + 9));
        const uint32_t r2 = pack2(WG(gg + 8, cc),     WG(gg + 8, cc + 1));
        const uint32_t r3 = pack2(WG(gg + 8, cc + 8), WG(gg + 8, cc + 9));
        #undef WG
        g_wf[i] = make_uint4(r0, r1, r2, r3);
    }
}

// ---- main ----
__global__ __launch_bounds__(256, 2)
void conv4d_hmma16r_kernel(const float* __restrict__ bias,
                           float* __restrict__ out) {
    extern __shared__ char smc[];
    const uint32_t slabAddr = smem_u32(smc);                 // slab | ws
    const uint32_t wsAddr   = slabAddr + SLABB;

    const int tid = threadIdx.x;
    const int wid = tid >> 5;
    const int l   = tid & 31;
    const int g   = l >> 2;
    const int c   = l & 3;
    const int wo  = wid >> 2;
    const int dp  = wid & 3;

    int bi = blockIdx.x;
    const int dt = bi % 3;  bi /= 3;
    const int wt = bi % 12; bi /= 12;
    const int h  = bi % 24; bi /= 24;
    const int b  = bi;
    const int d0 = dt * 8;
    const int w0 = wt * 2;

    // ldmatrix per-lane offset within the slab: half = l>>4, H rows = +24.
    const uint32_t aOff = (uint32_t)((l >> 4) * HALFB)
        + (uint32_t)(((wo * 10 + 2 * dp) * 24 + (l & 7) + ((l & 8) ? 24 : 0)) * 16);

    // valid kh planes
    int khs[3], nkh = 0;
    #pragma unroll
    for (int kh = 0; kh < 3; ++kh)
        if ((unsigned)(h + kh - 1) < 24u) khs[nkh++] = kh;

    const char* xhBase = (const char*)g_xh;
    const char* wfBase = (const char*)g_wf;

    float acc[3][2][4];
    #pragma unroll
    for (int j = 0; j < 3; ++j)
        #pragma unroll
        for (int u = 0; u < 2; ++u)
            #pragma unroll
            for (int q = 0; q < 4; ++q) acc[j][u][q] = 0.0f;

    for (int i = 0; i < nkh; ++i) {
        const int kh = khs[i];
        if (i > 0) __syncthreads();           // previous compute's smem reads done

        // ---- stage weights for this kh (contiguous 13824B) ----
        #pragma unroll
        for (int k = 0; k < 4; ++k) {
            const int ii = tid + k * 256;
            if (ii < 864)
                cpa16(wsAddr + (uint32_t)(ii * 16),
                      wfBase + (kh * 864 + ii) * 16, 16u);
        }
        // ---- stage slab: 5760 x 16B, aligned 3-copy layout ----
        {
            const char* sp = xhBase + (long long)((b * 24 + (h + kh - 1)) * 13824) * 32;
            #pragma unroll 4
            for (int k = 0; k < 23; ++k) {
                const int ii = tid + k * 256;
                if (ii < 5760) {
                    const int tI = ii % 24; int r = ii / 24;
                    const int dI = r % 10; r /= 10;
                    const int wI = r & 3;  r >>= 2;
                    const int o  = r & 1;
                    const int kt = r >> 1;
                    const int gw = w0 + wI - 1, gd = d0 + dI - 1, gt = tI - 1 + kt;
                    const uint32_t dst = slabAddr + (uint32_t)(kt * COPYB + o * HALFB
                                           + ((wI * 10 + dI) * 24 + tI) * 16);
                    const bool v = (unsigned)gw < 24u && (unsigned)gd < 24u
                                   && (unsigned)gt < 24u;
                    const char* src = sp + (v ? ((gw * 576 + gd * 24 + gt) * 32 + o * 16) : 0);
                    cpa16(dst, src, v ? 16u : 0u);
                }
            }
        }
        asm volatile("cp.async.commit_group;" ::: "memory");
        asm volatile("cp.async.wait_group 0;" ::: "memory");
        __syncthreads();

        // ---- compute: 27 taps x (1 LDS.128 + 3 LDSM.x4 + 6 HMMA) ----
        const uint32_t aLane = slabAddr + aOff;
        const uint32_t wLane = wsAddr + (uint32_t)(l * 16);
        #pragma unroll
        for (int tl = 0; tl < 27; ++tl) {
            const int kw = tl / 9, kd = (tl / 3) % 3, kt = tl % 3;
            uint32_t b0, b1, b2, b3;
            asm volatile("ld.shared.v4.b32 {%0,%1,%2,%3}, [%4];"
                         : "=r"(b0), "=r"(b1), "=r"(b2), "=r"(b3)
                         : "r"(wLane + (uint32_t)(tl * 512)));
            #pragma unroll
            for (int j = 0; j < 3; ++j) {
                const uint32_t P = (uint32_t)(kt * COPYB
                                              + (kw * 240 + kd * 24 + 8 * j) * 16);
                uint32_t a0, a1, a2, a3;
                asm volatile("ldmatrix.sync.aligned.m8n8.x4.shared.b16 {%0,%1,%2,%3}, [%4];"
                             : "=r"(a0), "=r"(a1), "=r"(a2), "=r"(a3)
                             : "r"(aLane + P));
                mma16816(acc[j][0], a0, a1, a2, a3, b0, b1);
                mma16816(acc[j][1], a0, a1, a2, a3, b2, b3);
            }
        }
    }

    // ---- epilogue ----
    float* ob = out + (size_t)b * 16 * ST_C + (size_t)h * ST_H + (size_t)(w0 + wo) * ST_W;
    const int dE = d0 + 2 * dp, dO = dE + 1;
    #pragma unroll
    for (int u = 0; u < 2; ++u) {
        const int co0 = u * 8 + 2 * c;
        const float b0v = bias[co0];
        const float b1v = bias[co0 + 1];
        #pragma unroll
        for (int j = 0; j < 3; ++j) {
            const int t = 8 * j + g;
            ob[(size_t)co0 * ST_C + (size_t)dE * ST_D + t]       = acc[j][u][0] + b0v;
            ob[(size_t)(co0 + 1) * ST_C + (size_t)dE * ST_D + t] = acc[j][u][1] + b1v;
            ob[(size_t)co0 * ST_C + (size_t)dO * ST_D + t]       = acc[j][u][2] + b0v;
            ob[(size_t)(co0 + 1) * ST_C + (size_t)dO * ST_D + t] = acc[j][u][3] + b1v;
        }
    }
}

extern "C" void kernel_launch(void* const* d_in, const int* in_sizes, int n_in,
                              void* d_out, int out_size) {
    const float* x   = (const float*)d_in[0];
    const float* w   = (const float*)d_in[1];
    const float* bia = (const float*)d_in[2];
    float* out       = (float*)d_out;

    prep_x_kernel<<<2592, 256>>>(x);
    prep_w_kernel<<<1, 256>>>(w);

    cudaFuncSetAttribute(conv4d_hmma16r_kernel,
                         cudaFuncAttributeMaxDynamicSharedMemorySize, SMEM_BYTES);
    conv4d_hmma16r_kernel<<<1728, 256, SMEM_BYTES>>>(bia, out);
}

// round 12
// speedup vs baseline: 2.1998x; 2.1998x over previous
#include <cuda_runtime.h>
#include <cuda_fp16.h>
#include <cstdint>

// fullConv4d via fp16 mma.sync m16n8k16 (fp32 accum). M=spatial, N=co, K=ci16.
// R12 = R9 structure (prep kernels + double-buffered cp.async slab, 2 CTA/SM)
// + kd-register-reuse: loop (kw,kt) outer, kd inner; tap kd's H matrices become
// tap kd+1's L matrices, so each kd step loads only one new d-row (ldmatrix.x2).

#define ST_T 1
#define ST_D 24
#define ST_W 576
#define ST_H 13824
#define ST_C 331776

#define SLABB   33280                       // 1040 pts * 32B
#define WSB     41472                       // 81 taps * 512B
#define SMEM_BYTES (2 * SLABB + WSB)        // 108032

__device__ uint4 g_xh[1327104];             // 663552 points * 32B (fp16, ci16)
__device__ uint4 g_wf[2592];                // 81 taps * 32 lanes * 16B

static __device__ __forceinline__ uint32_t smem_u32(const void* p) {
    uint32_t a;
    asm("{ .reg .u64 t; cvta.to.shared.u64 t, %1; cvt.u32.u64 %0, t; }" : "=r"(a) : "l"(p));
    return a;
}

static __device__ __forceinline__ uint32_t pack2(float a, float b) {
    __half2 h = __floats2half2_rn(a, b);
    return *reinterpret_cast<uint32_t*>(&h);
}

static __device__ __forceinline__ void cpa16(uint32_t dst, const void* src, uint32_t srcsz) {
    asm volatile("cp.async.cg.shared.global [%0], [%1], 16, %2;"
                 :: "r"(dst), "l"(src), "r"(srcsz));
}

static __device__ __forceinline__ void mma16816(float* d, uint32_t a0, uint32_t a1,
                                                uint32_t a2, uint32_t a3,
                                                uint32_t b0, uint32_t b1) {
    asm volatile(
        "mma.sync.aligned.m16n8k16.row.col.f32.f16.f16.f32 "
        "{%0,%1,%2,%3}, {%4,%5,%6,%7}, {%8,%9}, {%0,%1,%2,%3};"
        : "+f"(d[0]), "+f"(d[1]), "+f"(d[2]), "+f"(d[3])
        : "r"(a0), "r"(a1), "r"(a2), "r"(a3), "r"(b0), "r"(b1));
}

// ---- prep 1: x[b][ci][h][w][d][t] fp32 -> g_xh[(b,h,w,d,t)][ci16] fp16 ----
__global__ __launch_bounds__(256)
void prep_x_kernel(const float* __restrict__ x) {
    const int idx = blockIdx.x * 256 + threadIdx.x;          // 663552 points
    int r = idx;
    const int t = r % 24; r /= 24;
    const int d = r % 24; r /= 24;
    const int w = r % 24; r /= 24;
    const int h = r % 24;
    const int b = r / 24;
    const float* p = x + (size_t)b * 16 * ST_C + h * ST_H + w * ST_W + d * ST_D + t;
    uint32_t v[8];
    #pragma unroll
    for (int j = 0; j < 8; ++j)
        v[j] = pack2(p[(2 * j) * ST_C], p[(2 * j + 1) * ST_C]);
    g_xh[idx * 2]     = make_uint4(v[0], v[1], v[2], v[3]);
    g_xh[idx * 2 + 1] = make_uint4(v[4], v[5], v[6], v[7]);
}

// ---- prep 2: weights -> B-fragment order g_wf[tap][lane] ----
__global__ __launch_bounds__(256)
void prep_w_kernel(const float* __restrict__ wgt) {
    for (int i = threadIdx.x; i < 2592; i += 256) {
        const int tl = i >> 5, l5 = i & 31;
        const int gg = l5 >> 2, cc = (l5 & 3) << 1;
        const float* wp = wgt + tl;
        #define WG(co, ci) wp[((co) * 16 + (ci)) * 81]
        const uint32_t r0 = pack2(WG(gg, cc),         WG(gg, cc + 1));
        const uint32_t r1 = pack2(WG(gg, cc + 8),     WG(gg, cc + 9));
        const uint32_t r2 = pack2(WG(gg + 8, cc),     WG(gg + 8, cc + 1));
        const uint32_t r3 = pack2(WG(gg + 8, cc + 8), WG(gg + 8, cc + 9));
        #undef WG
        g_wf[i] = make_uint4(r0, r1, r2, r3);
    }
}

// ---- main ----
__global__ __launch_bounds__(256, 2)
void conv4d_hmma16s_kernel(const float* __restrict__ bias,
                           float* __restrict__ out) {
    extern __shared__ char smc[];
    const uint32_t slabAddr = smem_u32(smc);                 // buf0 | buf1 | ws
    const uint32_t wsAddr   = slabAddr + 2 * SLABB;

    const int tid = threadIdx.x;
    const int wid = tid >> 5;
    const int l   = tid & 31;
    const int g   = l >> 2;
    const int c   = l & 3;
    const int wo  = wid >> 2;
    const int dp  = wid & 3;

    int bi = blockIdx.x;
    const int dt = bi % 3;  bi /= 3;
    const int wt = bi % 12; bi /= 12;
    const int h  = bi % 24; bi /= 24;
    const int b  = bi;
    const int d0 = dt * 8;
    const int w0 = wt * 2;

    // x4 per-lane offset: lanes 0-7 L klo, 8-15 H(+26 rows) klo, 16-23 L khi, 24-31 H khi
    const int rowmap = (l & 8) ? (26 + (l & 7)) : (l & 7);
    const uint32_t aOff = (uint32_t)((wo * 260 + dp * 52 + rowmap) * 32 + (l >> 4) * 16);
    // x2 per-lane offset: lanes 0-7 new-d klo, lanes 8-15 new-d khi (row local offset added via P2)
    const uint32_t aOff2 = (uint32_t)((wo * 260 + dp * 52 + (l & 7)) * 32 + ((l >> 3) & 1) * 16);

    // ---- precompute staging slots ----
    uint32_t dstOff[9];
    int      srcRest[9];
    uint32_t inR = 0, gV = 0;
    #pragma unroll
    for (int k = 0; k < 9; ++k) {
        const int i = tid + k * 256;
        dstOff[k] = 0; srcRest[k] = 0;
        if (i < 2080) {
            const int o  = i & 1;
            const int pt = i >> 1;
            const int tI = pt % 26;
            const int rr = pt / 26;
            const int dI = rr % 10;
            const int wI = rr / 10;
            inR |= (1u << k);
            dstOff[k] = (uint32_t)(pt * 32 + o * 16);
            const int gw = w0 + wI - 1, gd = d0 + dI - 1, gt = tI - 1;
            if ((unsigned)gw < 24u && (unsigned)gd < 24u && (unsigned)gt < 24u) {
                srcRest[k] = (gw * 576 + gd * 24 + gt) * 32 + o * 16;
                gV |= (1u << k);
            }
        }
    }

    // valid kh planes
    int khs[3], nkh = 0;
    #pragma unroll
    for (int kh = 0; kh < 3; ++kh)
        if ((unsigned)(h + kh - 1) < 24u) khs[nkh++] = kh;

    const char* xhBase = (const char*)g_xh;

    auto stage_slab = [&](int kh, uint32_t bufAddr) {
        const char* sp = xhBase + (long long)((b * 24 + (h + kh - 1)) * 13824) * 32;
        #pragma unroll
        for (int k = 0; k < 9; ++k) {
            if (inR & (1u << k))
                cpa16(bufAddr + dstOff[k], sp + srcRest[k],
                      (gV & (1u << k)) ? 16u : 0u);
        }
    };

    // group 0: weights + slab khs[0]
    {
        const char* wf = (const char*)g_wf;
        #pragma unroll
        for (int k = 0; k < 11; ++k) {
            const int i = tid + k * 256;
            if (i < 2592) cpa16(wsAddr + (uint32_t)(i * 16), wf + i * 16, 16u);
        }
        stage_slab(khs[0], slabAddr);
        asm volatile("cp.async.commit_group;" ::: "memory");
    }
    // group 1: slab khs[1]
    if (nkh > 1) {
        stage_slab(khs[1], slabAddr + SLABB);
        asm volatile("cp.async.commit_group;" ::: "memory");
    }
    int issued = (nkh > 1) ? 2 : 1;

    float acc[3][2][4];
    #pragma unroll
    for (int j = 0; j < 3; ++j)
        #pragma unroll
        for (int u = 0; u < 2; ++u)
            #pragma unroll
            for (int q = 0; q < 4; ++q) acc[j][u][q] = 0.0f;

    for (int i = 0; i < nkh; ++i) {
        if (issued - i == 2) { asm volatile("cp.async.wait_group 1;" ::: "memory"); }
        else                 { asm volatile("cp.async.wait_group 0;" ::: "memory"); }
        __syncthreads();

        const uint32_t bufAddr = slabAddr + (uint32_t)((i & 1) * SLABB);
        const uint32_t aLane   = bufAddr + aOff;
        const uint32_t aLane2  = bufAddr + aOff2;
        const uint32_t wLane   = wsAddr + (uint32_t)(khs[i] * 27 * 512 + l * 16);

        #pragma unroll
        for (int kw = 0; kw < 3; ++kw) {
            #pragma unroll
            for (int kt = 0; kt < 3; ++kt) {
                const int kwb = kw * 260;
                // kd = 0: full x4 per j; keep H halves for reuse
                uint32_t hk0[3], hk1[3];     // per j: H klo / H khi
                {
                    uint32_t b0, b1, b2, b3;
                    asm volatile("ld.shared.v4.b32 {%0,%1,%2,%3}, [%4];"
                                 : "=r"(b0), "=r"(b1), "=r"(b2), "=r"(b3)
                                 : "r"(wLane + (uint32_t)((kw * 9 + kt) * 512)));
                    #pragma unroll
                    for (int j = 0; j < 3; ++j) {
                        const uint32_t P = (uint32_t)((kwb + kt + 8 * j) * 32);
                        uint32_t a0, a1, a2, a3;
                        asm volatile("ldmatrix.sync.aligned.m8n8.x4.shared.b16 "
                                     "{%0,%1,%2,%3}, [%4];"
                                     : "=r"(a0), "=r"(a1), "=r"(a2), "=r"(a3)
                                     : "r"(aLane + P));
                        mma16816(acc[j][0], a0, a1, a2, a3, b0, b1);
                        mma16816(acc[j][1], a0, a1, a2, a3, b2, b3);
                        hk0[j] = a1; hk1[j] = a3;
                    }
                }
                // kd = 1, 2: one new d-row per j via x2; prev H becomes L
                #pragma unroll
                for (int kd = 1; kd < 3; ++kd) {
                    uint32_t b0, b1, b2, b3;
                    asm volatile("ld.shared.v4.b32 {%0,%1,%2,%3}, [%4];"
                                 : "=r"(b0), "=r"(b1), "=r"(b2), "=r"(b3)
                                 : "r"(wLane + (uint32_t)((kw * 9 + kd * 3 + kt) * 512)));
                    #pragma unroll
                    for (int j = 0; j < 3; ++j) {
                        const uint32_t P2 = (uint32_t)((kwb + (kd + 1) * 26 + kt + 8 * j) * 32);
                        uint32_t n0, n1;
                        asm volatile("ldmatrix.sync.aligned.m8n8.x2.shared.b16 "
                                     "{%0,%1}, [%2];"
                                     : "=r"(n0), "=r"(n1)
                                     : "r"(aLane2 + P2));
                        mma16816(acc[j][0], hk0[j], n0, hk1[j], n1, b0, b1);
                        mma16816(acc[j][1], hk0[j], n0, hk1[j], n1, b2, b3);
                        hk0[j] = n0; hk1[j] = n1;
                    }
                }
            }
        }

        if (issued < nkh) {               // nkh==3: refill buf0 with khs[2]
            __syncthreads();
            stage_slab(khs[2], slabAddr);
            asm volatile("cp.async.commit_group;" ::: "memory");
            issued = 3;
        }
    }

    // ---- epilogue ----
    float* ob = out + (size_t)b * 16 * ST_C + (size_t)h * ST_H + (size_t)(w0 + wo) * ST_W;
    const int dE = d0 + 2 * dp, dO = dE + 1;
    #pragma unroll
    for (int u = 0; u < 2; ++u) {
        const int co0 = u * 8 + 2 * c;
        const float b0v = bias[co0];
        const float b1v = bias[co0 + 1];
        #pragma unroll
        for (int j = 0; j < 3; ++j) {
            const int t = 8 * j + g;
            ob[(size_t)co0 * ST_C + (size_t)dE * ST_D + t]       = acc[j][u][0] + b0v;
            ob[(size_t)(co0 + 1) * ST_C + (size_t)dE * ST_D + t] = acc[j][u][1] + b1v;
            ob[(size_t)co0 * ST_C + (size_t)dO * ST_D + t]       = acc[j][u][2] + b0v;
            ob[(size_t)(co0 + 1) * ST_C + (size_t)dO * ST_D + t] = acc[j][u][3] + b1v;
        }
    }
}

extern "C" void kernel_launch(void* const* d_in, const int* in_sizes, int n_in,
                              void* d_out, int out_size) {
    const float* x   = (const float*)d_in[0];
    const float* w   = (const float*)d_in[1];
    const float* bia = (const float*)d_in[2];
    float* out       = (float*)d_out;

    prep_x_kernel<<<2592, 256>>>(x);
    prep_w_kernel<<<1, 256>>>(w);

    cudaFuncSetAttribute(conv4d_hmma16s_kernel,
                         cudaFuncAttributeMaxDynamicSharedMemorySize, SMEM_BYTES);
    conv4d_hmma16s_kernel<<<1728, 256, SMEM_BYTES>>>(bia, out);
}